// round 2
// baseline (speedup 1.0000x reference)
#include <cuda_runtime.h>
#include <cstdint>
#include <cstddef>

#define DEVINL __device__ __forceinline__

// ---------------- problem constants ----------------
constexpr int Bn = 8, Sn = 2048, Hn = 1024, Pn = 320, Vn = 32000;
constexpr int Mrows = Bn * Pn;   // 2560
constexpr int Kdim = Hn;         // 1024

// ---------------- GEMM tiling ----------------
constexpr int MT = 128;
constexpr int NT = 128;
constexpr int KC = 32;                   // fp32 per K-stage (128 B per row)
constexpr int NS = 3;                    // pipeline stages
constexpr int NITERS = Kdim / KC;        // 32

constexpr int STAGE_A = MT * KC * 4;     // 16 KB
constexpr int STAGE_B = NT * KC * 4;     // 16 KB
constexpr int STAGE_BYTES = STAGE_A + STAGE_B;       // 32 KB
constexpr int SMEM_TOTAL = NS * STAGE_BYTES;         // 96 KB -> 2 CTAs/SM

// ---------------- scratch (device globals; no allocation anywhere) ----------------
__device__ __align__(1024) float g_W2T[(size_t)Vn * Kdim];   // 131 MB
__device__ __align__(1024) float g_W1T[(size_t)Hn * Kdim];   // 4 MB
__device__ __align__(1024) float g_Xg[(size_t)Mrows * Kdim]; // 10.5 MB
__device__ __align__(1024) float g_Hb[(size_t)Mrows * Kdim]; // 10.5 MB
__device__ int g_pos64;

// ---------------- PTX helpers (all valid at compute_103 base target) ----------------
DEVINL uint32_t smem_u32(const void* p) {
    uint32_t a;
    asm("{ .reg .u64 t; cvta.to.shared.u64 t, %1; cvt.u32.u64 %0, t; }" : "=r"(a) : "l"(p));
    return a;
}
DEVINL void cp16(uint32_t dst, const void* src) {
    asm volatile("cp.async.cg.shared.global [%0], [%1], 16;" :: "r"(dst), "l"(src) : "memory");
}
DEVINL void cp_commit() { asm volatile("cp.async.commit_group;" ::: "memory"); }
DEVINL void ldsm4(uint32_t& r0, uint32_t& r1, uint32_t& r2, uint32_t& r3, uint32_t a) {
    asm volatile("ldmatrix.sync.aligned.m8n8.x4.shared.b16 {%0,%1,%2,%3}, [%4];"
                 : "=r"(r0), "=r"(r1), "=r"(r2), "=r"(r3) : "r"(a));
}
DEVINL void mma_tf32(float& c0, float& c1, float& c2, float& c3,
                     uint32_t a0, uint32_t a1, uint32_t a2, uint32_t a3,
                     uint32_t b0, uint32_t b1) {
    asm volatile(
        "mma.sync.aligned.m16n8k8.row.col.f32.tf32.tf32.f32 "
        "{%0,%1,%2,%3}, {%4,%5,%6,%7}, {%8,%9}, {%0,%1,%2,%3};"
        : "+f"(c0), "+f"(c1), "+f"(c2), "+f"(c3)
        : "r"(a0), "r"(a1), "r"(a2), "r"(a3), "r"(b0), "r"(b1));
}

// ---------------- stage loader: A tile MT x KC, B tile NT x KC, K-major, pitch 4096B ----------------
// Swizzle within a 128B smem row: kb ^ ((row & 7) << 4). 16B-chunk granularity,
// conflict-free for both cp.async 16B stores and ldmatrix 16B-segment reads.
DEVINL void issue_stage(uint32_t sb, const char* Ab, const char* Bb, int it, int s, int tid) {
    uint32_t sa = sb + s * STAGE_BYTES;
    uint32_t sB = sa + STAGE_A;
    const char* ga = Ab + (size_t)it * (KC * 4);
    const char* gb = Bb + (size_t)it * (KC * 4);
#pragma unroll
    for (int i = 0; i < (MT * 8) / 256; i++) {       // 4 chunks per thread
        int idx = tid + i * 256;
        int row = idx >> 3, ch = idx & 7;
        cp16(sa + row * 128 + ((ch * 16) ^ ((row & 7) << 4)), ga + (size_t)row * 4096 + ch * 16);
    }
#pragma unroll
    for (int i = 0; i < (NT * 8) / 256; i++) {       // 4 chunks per thread
        int idx = tid + i * 256;
        int row = idx >> 3, ch = idx & 7;
        cp16(sB + row * 128 + ((ch * 16) ^ ((row & 7) << 4)), gb + (size_t)row * 4096 + ch * 16);
    }
}

// ---------------- TF32 mma.sync GEMM: C[m,n] = sum_k A[m,k]*Bmat[n,k] + bias[n] (opt ReLU) --------
// 8 warps: 2 (M) x 4 (N); warp tile 64x32 = 4 m16-tiles x 4 n8-tiles.
__global__ void __launch_bounds__(256, 2) gemm_tf32_kernel(
    const float* __restrict__ A, const float* __restrict__ Bmat,
    const float* __restrict__ bias, float* __restrict__ C,
    long long ldc, int do_relu)
{
    extern __shared__ __align__(1024) char smem[];
    uint32_t sb = smem_u32(smem);
    const int tid = threadIdx.x, wid = tid >> 5, lane = tid & 31;
    const int wm = wid & 1, wn = wid >> 1;
    const long long m0 = (long long)blockIdx.x * MT;
    const long long n0 = (long long)blockIdx.y * NT;

    const char* Ab = (const char*)(A + (size_t)m0 * Kdim);
    const char* Bb = (const char*)(Bmat + (size_t)n0 * Kdim);

    // ldmatrix per-lane addressing precompute
    const int sub = lane >> 3, r8 = lane & 7;
    const uint32_t kxor = (uint32_t)(r8 << 4);
    // A: reg i <- lanes 8i..8i+7. reg0:(m0..7,k0..3) reg1:(m8..15,k0..3) reg2:(m..,k4..7) reg3
    uint32_t aoff[4];
#pragma unroll
    for (int mt = 0; mt < 4; mt++)
        aoff[mt] = (uint32_t)((wm * 64 + mt * 16 + (sub & 1) * 8 + r8) * 128);
    const uint32_t akseg = (uint32_t)((sub >> 1) * 16);   // k sub-segment byte
    // B pair p: reg0:(n=2p*8.., k0..3) reg1:(2p, k4..7) reg2:(2p+1, k0..3) reg3:(2p+1, k4..7)
    uint32_t boff[2];
#pragma unroll
    for (int p = 0; p < 2; p++)
        boff[p] = (uint32_t)((wn * 32 + p * 16 + (sub >> 1) * 8 + r8) * 128);
    const uint32_t bkseg = (uint32_t)((sub & 1) * 16);

    float acc[4][4][4];
#pragma unroll
    for (int i = 0; i < 4; i++)
#pragma unroll
        for (int j = 0; j < 4; j++)
#pragma unroll
            for (int r = 0; r < 4; r++) acc[i][j][r] = 0.f;

    // prologue: NS-1 stages in flight
#pragma unroll
    for (int j = 0; j < NS - 1; j++) { issue_stage(sb, Ab, Bb, j, j, tid); cp_commit(); }

    for (int it = 0; it < NITERS; ++it) {
        asm volatile("cp.async.wait_group %0;" :: "n"(NS - 2) : "memory");
        __syncthreads();
        // issue next stage (slot was consumed last iteration; sync above protects it)
        {
            int jn = it + NS - 1;
            if (jn < NITERS) issue_stage(sb, Ab, Bb, jn, jn % NS, tid);
            cp_commit();
        }
        // compute current stage
        uint32_t sa = sb + (it % NS) * STAGE_BYTES;
        uint32_t sB = sa + STAGE_A;
#pragma unroll
        for (int ks = 0; ks < KC / 8; ks++) {
            const uint32_t kb = (uint32_t)(ks * 32);
            uint32_t a[4][4];
#pragma unroll
            for (int mt = 0; mt < 4; mt++)
                ldsm4(a[mt][0], a[mt][1], a[mt][2], a[mt][3],
                      sa + aoff[mt] + ((kb + akseg) ^ kxor));
            uint32_t b[4][2];
#pragma unroll
            for (int p = 0; p < 2; p++) {
                uint32_t r0, r1, r2, r3;
                ldsm4(r0, r1, r2, r3, sB + boff[p] + ((kb + bkseg) ^ kxor));
                b[2 * p][0] = r0; b[2 * p][1] = r1;
                b[2 * p + 1][0] = r2; b[2 * p + 1][1] = r3;
            }
#pragma unroll
            for (int mt = 0; mt < 4; mt++)
#pragma unroll
                for (int nt = 0; nt < 4; nt++)
                    mma_tf32(acc[mt][nt][0], acc[mt][nt][1], acc[mt][nt][2], acc[mt][nt][3],
                             a[mt][0], a[mt][1], a[mt][2], a[mt][3],
                             b[nt][0], b[nt][1]);
        }
    }

    // ---------------- epilogue: bias (+relu), direct global stores ----------------
    const int crow = lane >> 2, ccol2 = (lane & 3) * 2;
#pragma unroll
    for (int mt = 0; mt < 4; mt++) {
        long long r = m0 + wm * 64 + mt * 16 + crow;
#pragma unroll
        for (int nt = 0; nt < 4; nt++) {
            long long cc = n0 + wn * 32 + nt * 8 + ccol2;
            float2 bv = *reinterpret_cast<const float2*>(bias + cc);
            float2 o0, o1;
            o0.x = acc[mt][nt][0] + bv.x; o0.y = acc[mt][nt][1] + bv.y;
            o1.x = acc[mt][nt][2] + bv.x; o1.y = acc[mt][nt][3] + bv.y;
            if (do_relu) {
                o0.x = fmaxf(o0.x, 0.f); o0.y = fmaxf(o0.y, 0.f);
                o1.x = fmaxf(o1.x, 0.f); o1.y = fmaxf(o1.y, 0.f);
            }
            *reinterpret_cast<float2*>(C + (size_t)r * ldc + cc) = o0;
            *reinterpret_cast<float2*>(C + (size_t)(r + 8) * ldc + cc) = o1;
        }
    }
}

// ---------------- transpose [R,C] -> out[C,R] ----------------
__global__ void transpose_kernel(const float* __restrict__ in, float* __restrict__ out, int R, int C) {
    __shared__ float t[32][33];
    int c0 = blockIdx.x * 32, r0 = blockIdx.y * 32;
    int tx = threadIdx.x, ty = threadIdx.y;
#pragma unroll
    for (int j = 0; j < 32; j += 8)
        t[ty + j][tx] = in[(size_t)(r0 + ty + j) * C + (c0 + tx)];
    __syncthreads();
#pragma unroll
    for (int j = 0; j < 32; j += 8)
        out[(size_t)(c0 + ty + j) * R + (r0 + tx)] = t[tx][ty + j];
}

// ---------------- int64-vs-int32 position width probe ----------------
__global__ void detect_kernel(const unsigned long long* pp) {
    __shared__ int bad;
    if (threadIdx.x == 0) bad = 0;
    __syncthreads();
    int mybad = 0;
    for (int i = threadIdx.x; i < Mrows / 2; i += 256)
        if (pp[i] >= (1ull << 32)) mybad = 1;
    if (mybad) bad = 1;
    __syncthreads();
    if (threadIdx.x == 0) g_pos64 = bad ? 0 : 1;
}

// ---------------- gather: X[b, pos[b,p], :] -> g_Xg ----------------
__global__ void gather_kernel(const float* __restrict__ X, const void* __restrict__ pp) {
    int i = blockIdx.x;
    int b = i / Pn;
    long long pos = g_pos64 ? ((const long long*)pp)[i]
                            : (long long)((const int*)pp)[i];
    const float4* src = (const float4*)(X + ((size_t)b * Sn + (size_t)pos) * Hn);
    float4* dst = (float4*)(g_Xg + (size_t)i * Hn);
    dst[threadIdx.x] = src[threadIdx.x];
}

// ---------------- rowwise LayerNorm (in place on g_Hb) ----------------
__global__ void ln_kernel(const float* __restrict__ gamma, const float* __restrict__ beta) {
    int row = blockIdx.x, tid = threadIdx.x;
    float4* rp = (float4*)(g_Hb + (size_t)row * Hn);
    float4 v = rp[tid];
    float s = v.x + v.y + v.z + v.w;
    float q = v.x * v.x + v.y * v.y + v.z * v.z + v.w * v.w;
#pragma unroll
    for (int o = 16; o; o >>= 1) {
        s += __shfl_xor_sync(0xFFFFFFFFu, s, o);
        q += __shfl_xor_sync(0xFFFFFFFFu, q, o);
    }
    __shared__ float ss[8], sq[8];
    __shared__ float smu, sinv;
    int wid = tid >> 5, lid = tid & 31;
    if (lid == 0) { ss[wid] = s; sq[wid] = q; }
    __syncthreads();
    if (tid == 0) {
        float ts = 0.f, tq = 0.f;
#pragma unroll
        for (int w = 0; w < 8; w++) { ts += ss[w]; tq += sq[w]; }
        float mu = ts / Hn;
        float var = tq / Hn - mu * mu;
        smu = mu; sinv = rsqrtf(var + 1e-5f);
    }
    __syncthreads();
    float mu = smu, inv = sinv;
    float4 gv = ((const float4*)gamma)[tid];
    float4 bv = ((const float4*)beta)[tid];
    v.x = (v.x - mu) * inv * gv.x + bv.x;
    v.y = (v.y - mu) * inv * gv.y + bv.y;
    v.z = (v.z - mu) * inv * gv.z + bv.z;
    v.w = (v.w - mu) * inv * gv.w + bv.w;
    rp[tid] = v;
}

// ---------------- launch ----------------
extern "C" void kernel_launch(void* const* d_in, const int* in_sizes, int n_in,
                              void* d_out, int out_size) {
    const float* X     = (const float*)d_in[0];
    const void*  pos   = d_in[1];
    const float* W1    = (const float*)d_in[2];
    const float* b1    = (const float*)d_in[3];
    const float* gamma = (const float*)d_in[4];
    const float* beta  = (const float*)d_in[5];
    const float* W2    = (const float*)d_in[6];
    const float* b2    = (const float*)d_in[7];
    float* out = (float*)d_out;

    cudaFuncSetAttribute(gemm_tf32_kernel, cudaFuncAttributeMaxDynamicSharedMemorySize, SMEM_TOTAL);

    void *pW1T, *pW2T, *pXg, *pHb;
    cudaGetSymbolAddress(&pW1T, g_W1T);
    cudaGetSymbolAddress(&pW2T, g_W2T);
    cudaGetSymbolAddress(&pXg, g_Xg);
    cudaGetSymbolAddress(&pHb, g_Hb);

    dim3 tb(32, 8);
    transpose_kernel<<<dim3(Hn / 32, Hn / 32), tb>>>(W1, (float*)pW1T, Hn, Hn);
    transpose_kernel<<<dim3(Vn / 32, Hn / 32), tb>>>(W2, (float*)pW2T, Hn, Vn);
    detect_kernel<<<1, 256>>>((const unsigned long long*)pos);
    gather_kernel<<<Mrows, 256>>>(X, pos);

    // GEMM1: h_pre = relu(Xg @ W1 + b1) -> g_Hb
    gemm_tf32_kernel<<<dim3(Mrows / MT, Hn / NT), 256, SMEM_TOTAL>>>(
        (const float*)pXg, (const float*)pW1T, b1, (float*)pHb, (long long)Hn, 1);

    ln_kernel<<<Mrows, 256>>>(gamma, beta);

    // GEMM2: out = h @ W2 + b2
    gemm_tf32_kernel<<<dim3(Mrows / MT, Vn / NT), 256, SMEM_TOTAL>>>(
        (const float*)pHb, (const float*)pW2T, b2, out, (long long)Vn, 0);
}